// round 15
// baseline (speedup 1.0000x reference)
#include <cuda_runtime.h>
#include <cstdint>

#define THREADS 512
#define KDIM 120
#define INP 512
#define KC 24
#define NCHUNK 5
#define NJ2 12
#define X_STRIDE 1028                        // proven conflict-free plane layout

#define PLANE (NJ2 * X_STRIDE)               // 12336 floats
#define SCR_STRIDE 15                        // scratch [512][15] aliases plane (7680 < 12336)
#define SW7_OFF PLANE                        // [120][2] ull = 480 floats
#define PEX_OFF (SW7_OFF + 480)              // [512][10] = 5120 floats
#define RED_OFF (PEX_OFF + 5120)             // [16][16] = 256
#define RAW_OFF (RED_OFF + 256)              // [25]
#define SOUT_OFF (RAW_OFF + 32)              // [32]
#define SMEM_FLOATS (SOUT_OFF + 32)          // 18256
#define SMEM_BYTES (SMEM_FLOATS * 4)         // 73024

typedef unsigned long long ull;

// cW float view [120][32]: floats 0..13 = W cols 0..13; floats 16..26 = W cols 14..24;
// all else 0. Group g of k-row k: 3 LDC.128 at ulonglong2 (k*8 + g*4 + {0,1,2});
// 7th col-pair (floats 16g+12..13) staged to smem sW7 slot (k*2+g).
__constant__ ulonglong2 cW2[120 * 8];        // 15360 B, zero-init

__device__ __forceinline__ ull dup2(float v) {
    ull r;
    asm("mov.b64 %0, {%1, %1};" : "=l"(r) : "r"(__float_as_uint(v)));
    return r;
}
__device__ __forceinline__ void ffma2(ull& d, ull a, ull b) {
    asm("fma.rn.f32x2 %0, %1, %2, %0;" : "+l"(d) : "l"(a), "l"(b));
}
__device__ __forceinline__ void unpack2(ull v, float& lo, float& hi) {
    unsigned int a, b2;
    asm("mov.b64 {%0, %1}, %2;" : "=r"(a), "=r"(b2) : "l"(v));
    lo = __uint_as_float(a);
    hi = __uint_as_float(b2);
}

extern __shared__ float smem[];

__global__ void __launch_bounds__(THREADS, 2)
caps_kernel(const float* __restrict__ x, float* __restrict__ out)
{
    const int b    = blockIdx.x;
    const int t    = threadIdx.x;
    const int rt   = t & 255;          // row-thread: rows 2rt, 2rt+1
    const int gcol = t >> 8;           // 0: cols 0..13 ; 1: cols 14..24(+pads)
    const int lane = t & 31, wid = t >> 5;

    float* plane   = smem;                       // [NJ2][X_STRIDE]
    float* scratch = smem;                       // routing partials alias plane
    float* sW7     = smem + SW7_OFF;             // ull slot (k*2+g): 7th col-pair
    float* pexch   = smem + PEX_OFF;             // [512][10]
    float* red     = smem + RED_OFF;             // [16][16]
    float* raw     = smem + RAW_OFF;             // [25]
    float* sOut    = smem + SOUT_OFF;            // [25..32]

    // ---- stage sW7 from constant: ull index k*16 + g*8 + 6 -> slot k*2+g ----
    if (t < 240) {
        int k = t >> 1, g = t & 1;
        ull v = reinterpret_cast<const ull*>(cW2)[k * 16 + g * 8 + 6];
        *reinterpret_cast<ull*>(sW7 + t * 2) = v;
    }

    // ---- GEMM: u_hat[2 rows][my 14 cols] in 14 f32x2 accumulators ----
    ull acc[2][7];
    #pragma unroll
    for (int r = 0; r < 2; r++)
        #pragma unroll
        for (int p = 0; p < 7; p++) acc[r][p] = 0ull;

    const float4* xg = reinterpret_cast<const float4*>(x) + (size_t)b * (INP * KDIM / 4);

    for (int kc = 0; kc < NCHUNK; kc++) {
        __syncthreads();                 // plane safe to overwrite (first pass: sW7 visible)
        const int k0q = kc * (KC / 4);
        #pragma unroll
        for (int it2 = 0; it2 < 6; it2++) {        // FIXED: 3072 float4 = 6 x 512 threads
            int idx  = t + it2 * THREADS;
            int row  = idx / (KC / 4);
            int slot = idx % (KC / 4);
            float4 v = xg[row * (KDIM / 4) + k0q + slot];
            float* p0 = plane + (2 * slot) * X_STRIDE + (row >> 1) * 4 + (row & 1) * 2;
            *reinterpret_cast<float2*>(p0)            = make_float2(v.x, v.y);  // j2=2slot
            *reinterpret_cast<float2*>(p0 + X_STRIDE) = make_float2(v.z, v.w);  // j2=2slot+1
        }
        __syncthreads();

        const ulonglong2* wb = cW2 + kc * KC * 8 + gcol * 4;
        const float* s7b = sW7 + kc * KC * 4 + gcol * 2;   // slot(k,g) float off = 4k+2g
        #pragma unroll
        for (int j2 = 0; j2 < NJ2; j2++) {
            // {x(k0,r0), x(k1,r0), x(k0,r1), x(k1,r1)}
            float4 xv = *reinterpret_cast<const float4*>(plane + j2 * X_STRIDE + rt * 4);
            ull a0 = dup2(xv.x);   // k0, row0
            ull a1 = dup2(xv.y);   // k1, row0
            ull b0 = dup2(xv.z);   // k0, row1
            ull b1 = dup2(xv.w);   // k1, row1

            const ulonglong2* w0 = wb + (2 * j2) * 8;       // k0 row, my group
            const ulonglong2* w1 = w0 + 8;                  // k1 row
            // k0: pairs 0..5 via LDC.128, pair 6 via smem broadcast
            #pragma unroll
            for (int m = 0; m < 3; m++) {
                ulonglong2 v = w0[m];
                ffma2(acc[0][2 * m],     a0, v.x);
                ffma2(acc[1][2 * m],     b0, v.x);
                ffma2(acc[0][2 * m + 1], a0, v.y);
                ffma2(acc[1][2 * m + 1], b0, v.y);
            }
            {
                ull v7 = *reinterpret_cast<const ull*>(s7b + (2 * j2) * 4);
                ffma2(acc[0][6], a0, v7);
                ffma2(acc[1][6], b0, v7);
            }
            // k1
            #pragma unroll
            for (int m = 0; m < 3; m++) {
                ulonglong2 v = w1[m];
                ffma2(acc[0][2 * m],     a1, v.x);
                ffma2(acc[1][2 * m],     b1, v.x);
                ffma2(acc[0][2 * m + 1], a1, v.y);
                ffma2(acc[1][2 * m + 1], b1, v.y);
            }
            {
                ull v7 = *reinterpret_cast<const ull*>(s7b + (2 * j2 + 1) * 4);
                ffma2(acc[0][6], a1, v7);
                ffma2(acc[1][6], b1, v7);
            }
        }
    }
    __syncthreads();

    // ---- unpack u_hat (local cols; group1 pads are exact zeros) ----
    float u[2][14];
    #pragma unroll
    for (int r = 0; r < 2; r++)
        #pragma unroll
        for (int p = 0; p < 7; p++)
            unpack2(acc[r][p], u[r][2 * p], u[r][2 * p + 1]);

    float bb[2][5];
    #pragma unroll
    for (int r = 0; r < 2; r++)
        #pragma unroll
        for (int i = 0; i < 5; i++) bb[r][i] = 0.f;

    const int gbase = gcol * 14;
    const int cmax  = gcol ? 11 : 14;     // valid global cols per group (warp-uniform)

    // ---- 4 routing iterations ----
    for (int it = 0; it < 4; it++) {
        float cw[2][5];
        #pragma unroll
        for (int r = 0; r < 2; r++) {
            float m = bb[r][0];
            #pragma unroll
            for (int i = 1; i < 5; i++) m = fmaxf(m, bb[r][i]);
            float e[5], s = 0.f;
            #pragma unroll
            for (int i = 0; i < 5; i++) { e[i] = __expf(bb[r][i] - m); s += e[i]; }
            float inv = 1.f / s;
            #pragma unroll
            for (int i = 0; i < 5; i++) cw[r][i] = e[i] * inv;
        }
        // per-thread partials (u==0 on pads makes them contribute exactly 0)
        #pragma unroll
        for (int c = 0; c < 14; c++) {
            int cap = ((gbase + c) >= 25) ? 4 : (gbase + c) / 5;   // clamp; u is 0 there
            scratch[t * SCR_STRIDE + c] = cw[0][cap] * u[0][c] + cw[1][cap] * u[1][c];
        }
        __syncthreads();
        if (lane < 14) {
            float s = 0.f;
            #pragma unroll
            for (int uu = 0; uu < 32; uu++) s += scratch[(wid * 32 + uu) * SCR_STRIDE + lane];
            red[wid * 16 + lane] = s;
        }
        __syncthreads();
        if (t < 25) {
            int grp = (t < 14) ? 0 : 1;
            int loc = t - grp * 14;
            float s = 0.f;
            #pragma unroll
            for (int ww = 0; ww < 8; ww++) s += red[(grp * 8 + ww) * 16 + loc];
            raw[t] = s;
        }
        __syncthreads();
        if (t < 25) {
            int i5 = (t / 5) * 5;
            float sq = 0.f;
            #pragma unroll
            for (int k = 0; k < 5; k++) { float v = raw[i5 + k]; sq += v * v; }
            sOut[t] = raw[t] * rsqrtf(sq + 1e-7f);   // squash = pure norm-normalization
        }
        __syncthreads();
        if (it < 3) {
            // partial b over my cols, then exchange with partner (other col-group)
            float pb[2][5];
            #pragma unroll
            for (int r = 0; r < 2; r++)
                #pragma unroll
                for (int i = 0; i < 5; i++) pb[r][i] = 0.f;
            for (int c = 0; c < cmax; c++) {       // warp-uniform bound
                int g = gbase + c;
                int cap = g / 5;
                float ov = sOut[g];
                pb[0][cap] += ov * u[0][c];
                pb[1][cap] += ov * u[1][c];
            }
            #pragma unroll
            for (int r = 0; r < 2; r++)
                #pragma unroll
                for (int i = 0; i < 5; i++)
                    pexch[t * 10 + r * 5 + i] = pb[r][i];
            __syncthreads();
            int prt = t ^ 256;
            #pragma unroll
            for (int r = 0; r < 2; r++)
                #pragma unroll
                for (int i = 0; i < 5; i++)
                    bb[r][i] = pb[r][i] + pexch[prt * 10 + r * 5 + i];  // b REPLACED
            __syncthreads();
        }
    }

    if (t < 25) out[b * 25 + t] = sOut[t];
}

extern "C" void kernel_launch(void* const* d_in, const int* in_sizes, int n_in,
                              void* d_out, int out_size)
{
    const float* x = (const float*)d_in[0];
    const float* W = (const float*)d_in[1];
    float* out = (float*)d_out;

    // Pack W[120][25] into cW2 float view [120][32]:
    //   cols 0..13  -> floats 0..13
    //   cols 14..24 -> floats 16..26     (pads stay zero from static init)
    void* csym = nullptr;
    cudaGetSymbolAddress(&csym, cW2);
    cudaMemcpy2DAsync(csym, 128,
                      W, 25 * sizeof(float),
                      14 * sizeof(float), KDIM,
                      cudaMemcpyDeviceToDevice, 0);
    cudaMemcpy2DAsync((char*)csym + 64, 128,
                      (const char*)W + 14 * sizeof(float), 25 * sizeof(float),
                      11 * sizeof(float), KDIM,
                      cudaMemcpyDeviceToDevice, 0);

    cudaFuncSetAttribute(caps_kernel, cudaFuncAttributeMaxDynamicSharedMemorySize, SMEM_BYTES);
    caps_kernel<<<1024, THREADS, SMEM_BYTES>>>(x, out);
}

// round 16
// speedup vs baseline: 1.3827x; 1.3827x over previous
#include <cuda_runtime.h>
#include <cstdint>

#define THREADS 512
#define KDIM 120
#define INP 512
#define KC 24
#define NCHUNK 5
#define NJ2 12
#define X_STRIDE 1026                        // float2/row; odd*2 -> conflict-free 8B lanes

#define PLANE (NJ2 * X_STRIDE)               // 12312 floats
#define SCR_STRIDE 27
#define REGION_A 13824                       // max(plane, scratch 512*27)
#define SW_OFF REGION_A                      // sW [120][16] floats (pairs 6..12 + pad)
#define RED_OFF (SW_OFF + 1920)              // [16][26]
#define RAW_OFF (RED_OFF + 16 * 26)
#define SOUT_OFF (RAW_OFF + 32)
#define SMEM_FLOATS (SOUT_OFF + 32)          // 16240
#define SMEM_BYTES (SMEM_FLOATS * 4)         // 64960

typedef unsigned long long ull;

// cWc[k*3 + m] = W k-row, col-pairs (2m, 2m+1), m=0..2 -> cols 0..11
__constant__ ulonglong2 cWc[120 * 3];        // 5760 B

__device__ __forceinline__ ull dup2(float v) {
    ull r;
    asm("mov.b64 %0, {%1, %1};" : "=l"(r) : "r"(__float_as_uint(v)));
    return r;
}
__device__ __forceinline__ void ffma2(ull& d, ull a, ull b) {
    asm("fma.rn.f32x2 %0, %1, %2, %0;" : "+l"(d) : "l"(a), "l"(b));
}
__device__ __forceinline__ void unpack2(ull v, float& lo, float& hi) {
    unsigned int a, b2;
    asm("mov.b64 {%0, %1}, %2;" : "=r"(a), "=r"(b2) : "l"(v));
    lo = __uint_as_float(a);
    hi = __uint_as_float(b2);
}

extern __shared__ float smem[];

__global__ void __launch_bounds__(THREADS, 2)
caps_kernel(const float* __restrict__ x, const float* __restrict__ W, float* __restrict__ out)
{
    const int b    = blockIdx.x;
    const int t    = threadIdx.x;      // owns row t
    const int lane = t & 31, wid = t >> 5;

    float* plane   = smem;                       // [NJ2][X_STRIDE] float2-per-row
    float* scratch = smem;                       // [512][27] aliases plane (GEMM done)
    float* sW      = smem + SW_OFF;              // [120][16]: col 12+f at float f (f<13), pad 0
    float* red     = smem + RED_OFF;             // [16][26]
    float* raw     = smem + RAW_OFF;             // [25]
    float* sOut    = smem + SOUT_OFF;            // [25]

    // ---- stage sW from gmem W: k-row k, float f -> col 12+f (f<13), else 0 ----
    for (int i = t; i < KDIM * 16; i += THREADS) {
        int k = i >> 4, f = i & 15;
        sW[i] = (f < 13) ? W[k * 25 + 12 + f] : 0.f;
    }

    // ---- GEMM: u_hat[1 row][26 cols] in 13 f32x2 accumulators ----
    ull acc[13];
    #pragma unroll
    for (int p = 0; p < 13; p++) acc[p] = 0ull;

    const float4* xg = reinterpret_cast<const float4*>(x) + (size_t)b * (INP * KDIM / 4);

    for (int kc = 0; kc < NCHUNK; kc++) {
        __syncthreads();                 // plane safe to overwrite (first pass: sW visible)
        const int k0q = kc * (KC / 4);
        #pragma unroll
        for (int it2 = 0; it2 < 6; it2++) {        // 3072 float4 = 6 x 512 threads
            int idx  = t + it2 * THREADS;
            int row  = idx / (KC / 4);
            int slot = idx % (KC / 4);
            float4 v = xg[row * (KDIM / 4) + k0q + slot];
            float* p0 = plane + (2 * slot) * X_STRIDE + row * 2;
            *reinterpret_cast<float2*>(p0)            = make_float2(v.x, v.y);  // j2=2slot
            *reinterpret_cast<float2*>(p0 + X_STRIDE) = make_float2(v.z, v.w);  // j2=2slot+1
        }
        __syncthreads();

        #pragma unroll
        for (int j2 = 0; j2 < NJ2; j2++) {
            const int kk0 = kc * KC + 2 * j2;
            // {x(k0,row t), x(k1,row t)}
            float2 xv = *reinterpret_cast<const float2*>(plane + j2 * X_STRIDE + 2 * t);
            ull a0 = dup2(xv.x);
            ull a1 = dup2(xv.y);

            #pragma unroll
            for (int dk = 0; dk < 2; dk++) {
                ull a = dk ? a1 : a0;
                const ulonglong2* wc = cWc + (kk0 + dk) * 3;
                const float* ws = sW + (kk0 + dk) * 16;
                // pairs 0..5 via LDC.128
                #pragma unroll
                for (int m = 0; m < 3; m++) {
                    ulonglong2 v = wc[m];
                    ffma2(acc[2 * m],     a, v.x);
                    ffma2(acc[2 * m + 1], a, v.y);
                }
                // pairs 6..11 via uniform LDS.128 broadcast
                #pragma unroll
                for (int m = 0; m < 3; m++) {
                    ulonglong2 v = *reinterpret_cast<const ulonglong2*>(ws + m * 4);
                    ffma2(acc[6 + 2 * m], a, v.x);
                    ffma2(acc[7 + 2 * m], a, v.y);
                }
                // pair 12 (cols 24, 25-pad) via LDS.64 broadcast
                {
                    ull v = *reinterpret_cast<const ull*>(ws + 12);
                    ffma2(acc[12], a, v);
                }
            }
        }
    }
    __syncthreads();

    // ---- unpack u_hat (col 25 is exact zero) ----
    float u[26];
    #pragma unroll
    for (int p = 0; p < 13; p++) unpack2(acc[p], u[2 * p], u[2 * p + 1]);

    float bb[5];
    #pragma unroll
    for (int i = 0; i < 5; i++) bb[i] = 0.f;

    // ---- 4 routing iterations ----
    for (int it = 0; it < 4; it++) {
        // softmax over 5 capsules for my row
        float cw[5];
        {
            float m = bb[0];
            #pragma unroll
            for (int i = 1; i < 5; i++) m = fmaxf(m, bb[i]);
            float e[5], s = 0.f;
            #pragma unroll
            for (int i = 0; i < 5; i++) { e[i] = __expf(bb[i] - m); s += e[i]; }
            float inv = 1.f / s;
            #pragma unroll
            for (int i = 0; i < 5; i++) cw[i] = e[i] * inv;
        }
        #pragma unroll
        for (int c = 0; c < 25; c++)
            scratch[t * SCR_STRIDE + c] = cw[c / 5] * u[c];
        __syncthreads();
        if (lane < 25) {
            float s = 0.f;
            #pragma unroll
            for (int uu = 0; uu < 32; uu++) s += scratch[(wid * 32 + uu) * SCR_STRIDE + lane];
            red[wid * 26 + lane] = s;
        }
        __syncthreads();
        if (t < 25) {
            float s = 0.f;
            #pragma unroll
            for (int gg = 0; gg < 16; gg++) s += red[gg * 26 + t];
            raw[t] = s;
        }
        __syncthreads();
        if (t < 25) {
            int i5 = (t / 5) * 5;
            float sq = 0.f;
            #pragma unroll
            for (int k = 0; k < 5; k++) { float v = raw[i5 + k]; sq += v * v; }
            sOut[t] = raw[t] * rsqrtf(sq + 1e-7f);   // squash = pure norm-normalization
        }
        __syncthreads();
        if (it < 3) {
            float ov[25];
            #pragma unroll
            for (int c = 0; c < 25; c++) ov[c] = sOut[c];
            #pragma unroll
            for (int i = 0; i < 5; i++) {
                float s = 0.f;
                #pragma unroll
                for (int k = 0; k < 5; k++) s += ov[i * 5 + k] * u[i * 5 + k];
                bb[i] = s;   // b REPLACED each iteration (matches reference)
            }
            __syncthreads();
        }
    }

    if (t < 25) out[b * 25 + t] = sOut[t];
}

extern "C" void kernel_launch(void* const* d_in, const int* in_sizes, int n_in,
                              void* d_out, int out_size)
{
    const float* x = (const float*)d_in[0];
    const float* W = (const float*)d_in[1];
    float* out = (float*)d_out;

    // cWc: W cols 0..11 per k-row (48B/row)
    void* csym = nullptr;
    cudaGetSymbolAddress(&csym, cWc);
    cudaMemcpy2DAsync(csym, 48,
                      W, 25 * sizeof(float),
                      48, KDIM,
                      cudaMemcpyDeviceToDevice, 0);

    cudaFuncSetAttribute(caps_kernel, cudaFuncAttributeMaxDynamicSharedMemorySize, SMEM_BYTES);
    caps_kernel<<<1024, THREADS, SMEM_BYTES>>>(x, W, out);
}